// round 16
// baseline (speedup 1.0000x reference)
#include <cuda_runtime.h>
#include <cuda_fp16.h>
#include <stdint.h>

#define BATCH 8
#define NN 2048
#define IN_DIM 128
#define OUT_DIM 64
#define NEG_SLOPE 0.2f
#define JSPLIT 4
#define TOT (BATCH * NN * OUT_DIM)
#define NWORDS (NN / 32)          // 64 bit-words per adj row
#define H_BLOCKS (BATCH * NN / 32)   // 512

// ---- device scratch (allocation-free rule) ----
__device__ __half g_h[BATCH * NN * OUT_DIM];       // 2 MB, h fp16 [b][n][d]
__device__ uint32_t g_adjbits[NN * NWORDS];        // 512 KB packed adjacency
__device__ float g_fi[BATCH * NN];
__device__ float g_fj[BATCH * NN];
__device__ float g_E1[BATCH * NN];                 // exp(fj)
__device__ float g_E2[BATCH * NN];                 // exp(0.2*fj)
__device__ float g_c1[BATCH * NN];                 // sinv * exp(fi - m)
__device__ float g_c2[BATCH * NN];                 // sinv * exp(0.2*fi - m)
__device__ float g_t[BATCH * NN];                  // exp(-fi)  (branch threshold)
__device__ float g_out_part[JSPLIT * TOT];         // 16 MB
__device__ int   g_arrive[(NN / 64) * BATCH];      // zero-init; reset after use

__device__ __forceinline__ float neg_inf_f() { return __int_as_float(0xff800000); }

// ---- tensor-core helpers (sm_80+ ISA: valid on base sm_100 target) ----
__device__ __forceinline__ void ldsm_x4(uint32_t& r0, uint32_t& r1, uint32_t& r2, uint32_t& r3,
                                        uint32_t addr) {
    asm volatile("ldmatrix.sync.aligned.m8n8.x4.shared.b16 {%0,%1,%2,%3}, [%4];"
                 : "=r"(r0), "=r"(r1), "=r"(r2), "=r"(r3) : "r"(addr));
}
__device__ __forceinline__ void ldsm_x4_t(uint32_t& r0, uint32_t& r1, uint32_t& r2, uint32_t& r3,
                                          uint32_t addr) {
    asm volatile("ldmatrix.sync.aligned.m8n8.x4.trans.shared.b16 {%0,%1,%2,%3}, [%4];"
                 : "=r"(r0), "=r"(r1), "=r"(r2), "=r"(r3) : "r"(addr));
}
__device__ __forceinline__ void mma16816h(float* c, const uint32_t* a, uint32_t b0, uint32_t b1) {
    asm volatile(
        "mma.sync.aligned.m16n8k16.row.col.f32.f16.f16.f32 "
        "{%0,%1,%2,%3}, {%4,%5,%6,%7}, {%8,%9}, {%0,%1,%2,%3};"
        : "+f"(c[0]), "+f"(c[1]), "+f"(c[2]), "+f"(c[3])
        : "r"(a[0]), "r"(a[1]), "r"(a[2]), "r"(a[3]), "r"(b0), "r"(b1));
}

// ============================================================================
// Kernel PH (fused): blocks [0, 512) compute h/fi/fj/E1/E2; blocks [512, 1536)
// pack adj into bits (2 threads per word). Independent work, overlapped.
// ============================================================================
__global__ void __launch_bounds__(256) gat_prep_kernel(
    const float* __restrict__ x, const float* __restrict__ W,
    const float* __restrict__ a, const float* __restrict__ adj)
{
    __shared__ float W_s[IN_DIM * OUT_DIM];
    int tid = threadIdx.x;

    if (blockIdx.x >= H_BLOCKS) {
        // ---- pack body ----
        int gt = (blockIdx.x - H_BLOCKS) * 256 + tid;
        int wi = gt >> 1;
        int half = gt & 1;
        const float4* src = (const float4*)adj + (size_t)wi * 8 + half * 4;
        uint32_t bits = 0;
#pragma unroll
        for (int q = 0; q < 4; q++) {
            float4 v = src[q];
            if (v.x != 0.0f) bits |= 1u << (q * 4 + 0);
            if (v.y != 0.0f) bits |= 1u << (q * 4 + 1);
            if (v.z != 0.0f) bits |= 1u << (q * 4 + 2);
            if (v.w != 0.0f) bits |= 1u << (q * 4 + 3);
        }
        uint32_t other = __shfl_down_sync(0xffffffffu, bits, 1);
        if (half == 0) g_adjbits[wi] = bits | (other << 16);
        return;
    }

    // ---- h body ----
    {
        const float4* Wv = (const float4*)W;
        float4* Wsv = (float4*)W_s;
#pragma unroll
        for (int i = 0; i < 8; i++) Wsv[tid + i * 256] = Wv[tid + i * 256];
    }
    __syncthreads();

    int r = tid >> 3;
    int dg = (tid & 7) * 8;
    int row = blockIdx.x * 32 + r;
    const float4* xrow4 = (const float4*)(x + (size_t)row * IN_DIM);

    float acc[8];
#pragma unroll
    for (int d = 0; d < 8; d++) acc[d] = 0.0f;

#pragma unroll 4
    for (int k4 = 0; k4 < IN_DIM / 4; k4++) {
        float4 xv = __ldg(&xrow4[k4]);
        const float* wr0 = &W_s[(k4 * 4 + 0) * OUT_DIM + dg];
        const float* wr1 = &W_s[(k4 * 4 + 1) * OUT_DIM + dg];
        const float* wr2 = &W_s[(k4 * 4 + 2) * OUT_DIM + dg];
        const float* wr3 = &W_s[(k4 * 4 + 3) * OUT_DIM + dg];
#pragma unroll
        for (int d = 0; d < 8; d++) {
            acc[d] = fmaf(xv.x, wr0[d], acc[d]);
            acc[d] = fmaf(xv.y, wr1[d], acc[d]);
            acc[d] = fmaf(xv.z, wr2[d], acc[d]);
            acc[d] = fmaf(xv.w, wr3[d], acc[d]);
        }
    }

    {
        uint32_t uh[4];
#pragma unroll
        for (int p = 0; p < 4; p++) {
            __half2 hp = __float22half2_rn(make_float2(acc[2 * p], acc[2 * p + 1]));
            uh[p] = *(uint32_t*)&hp;
        }
        *(uint4*)(g_h + (size_t)row * OUT_DIM + dg) = make_uint4(uh[0], uh[1], uh[2], uh[3]);
    }

    float fi = 0.0f, fj = 0.0f;
#pragma unroll
    for (int d = 0; d < 8; d++) {
        fi = fmaf(acc[d], __ldg(&a[dg + d]), fi);
        fj = fmaf(acc[d], __ldg(&a[OUT_DIM + dg + d]), fj);
    }
#pragma unroll
    for (int off = 4; off > 0; off >>= 1) {
        fi += __shfl_down_sync(0xffffffffu, fi, off);
        fj += __shfl_down_sync(0xffffffffu, fj, off);
    }
    if ((tid & 7) == 0) {
        g_fi[row] = fi;
        g_fj[row] = fj;
        g_E1[row] = __expf(fj);
        g_E2[row] = __expf(NEG_SLOPE * fj);
    }
}

// ============================================================================
// Kernel B: stats via exp factorization — NO MUFU in the sweep.
// ============================================================================
__global__ void __launch_bounds__(256) gat_stats_kernel()
{
    __shared__ __align__(16) float fj_s[NN];   // for fjmax only
    __shared__ __align__(16) float E1_s[NN];
    __shared__ __align__(16) float E2_s[NN];
    __shared__ float red_s[8];

    int tid = threadIdx.x, lane = tid & 31, w = tid >> 5;
    int b = blockIdx.y;
    int i0 = blockIdx.x * 32;

#pragma unroll
    for (int k = 0; k < 2; k++) {
        ((float4*)fj_s)[tid + k * 256] = ((const float4*)(g_fj + (size_t)b * NN))[tid + k * 256];
        ((float4*)E1_s)[tid + k * 256] = ((const float4*)(g_E1 + (size_t)b * NN))[tid + k * 256];
        ((float4*)E2_s)[tid + k * 256] = ((const float4*)(g_E2 + (size_t)b * NN))[tid + k * 256];
    }
    __syncthreads();

    float lm = neg_inf_f();
#pragma unroll
    for (int k = 0; k < 8; k++) lm = fmaxf(lm, fj_s[tid + k * 256]);
#pragma unroll
    for (int off = 16; off > 0; off >>= 1)
        lm = fmaxf(lm, __shfl_xor_sync(0xffffffffu, lm, off));
    if (lane == 0) red_s[w] = lm;
    __syncthreads();
    float fjmax = red_s[0];
#pragma unroll
    for (int q = 1; q < 8; q++) fjmax = fmaxf(fjmax, red_s[q]);

#pragma unroll 1
    for (int rr = 0; rr < 4; rr++) {
        int r = w * 4 + rr;
        int grow = b * NN + i0 + r;
        float fi = g_fi[grow];
        float m = fi + fjmax;
        m = fmaxf(m, NEG_SLOPE * m);
        float a1 = __expf(fi - m);
        float a2 = __expf(NEG_SLOPE * fi - m);
        float t  = __expf(-fi);
        const uint32_t* brow = g_adjbits + (size_t)(i0 + r) * NWORDS;

        float S1a = 0.0f, S1b = 0.0f, S2a = 0.0f, S2b = 0.0f;
#pragma unroll 2
        for (int j = lane * 4; j < NN; j += 128) {
            uint32_t wb = __ldg(&brow[j >> 5]);
            uint32_t b4 = (wb >> (j & 31)) & 0xFu;
            float4 e1 = *(const float4*)&E1_s[j];
            float4 e2 = *(const float4*)&E2_s[j];
            if (b4 & 1u) { if (e1.x >= t) S1a += e1.x; else S2a += e2.x; }
            if (b4 & 2u) { if (e1.y >= t) S1b += e1.y; else S2b += e2.y; }
            if (b4 & 4u) { if (e1.z >= t) S1a += e1.z; else S2a += e2.z; }
            if (b4 & 8u) { if (e1.w >= t) S1b += e1.w; else S2b += e2.w; }
        }
        float s = a1 * (S1a + S1b) + a2 * (S2a + S2b);
#pragma unroll
        for (int off = 16; off > 0; off >>= 1)
            s += __shfl_xor_sync(0xffffffffu, s, off);

        if (lane == 0) {
            float si = (s > 0.0f) ? (1.0f / s) : 0.0f;
            g_c1[grow] = si * a1;
            g_c2[grow] = si * a2;
            g_t[grow]  = t;
        }
    }
}

// ============================================================================
// Kernel C: alpha + mma (R15 inner loops) + atomic-counter tail reduction.
// Grid (32 i-tiles of 64, 4 j-quarters, 8 batches) = 1024 blocks.
// Last-arriving block per (i-tile, b) sums the 4 partials (L2-hot) -> out.
// ============================================================================
#define TSA 136   // a_s stride in fp16 (272 B/row)
#define TSH 72    // h_s stride in fp16 (144 B/row)

__global__ void __launch_bounds__(256) gat_acc_kernel(
    float* __restrict__ out, float* __restrict__ alpha_out)
{
    __shared__ __align__(16) float E1_s[512];
    __shared__ __align__(16) float E2_s[512];
    __shared__ float c1_s[64], c2_s[64], t_s[64];
    __shared__ __align__(16) __half a_s[64 * TSA];    // 17408 B
    __shared__ __align__(16) __half h_s[128 * TSH];   // 18432 B
    __shared__ int last_s;

    int tid = threadIdx.x, lane = tid & 31, w = tid >> 5;
    int i0 = blockIdx.x * 64;
    int jq = blockIdx.y;
    int b  = blockIdx.z;
    int jbase = jq * 512;

    ((float2*)E1_s)[tid] = ((const float2*)(g_E1 + (size_t)b * NN + jbase))[tid];
    ((float2*)E2_s)[tid] = ((const float2*)(g_E2 + (size_t)b * NN + jbase))[tid];
    if (tid < 64) {
        int grow = b * NN + i0 + tid;
        c1_s[tid] = g_c1[grow];
        c2_s[tid] = g_c2[grow];
        t_s[tid]  = g_t[grow];
    }

    const uint32_t aB = (uint32_t)__cvta_generic_to_shared(a_s);
    const uint32_t hB = (uint32_t)__cvta_generic_to_shared(h_s);
    const uint32_t laneA = (uint32_t)((lane & 15) * (TSA * 2) + (lane >> 4) * 16);
    const uint32_t laneH = (uint32_t)((lane & 15) * (TSH * 2) + (lane >> 4) * 16);

    const int m0 = (w & 3) * 16;      // warp's m-strip
    const int nb = (w >> 2) * 32;     // warp's n-half

    float acc[4][4];
#pragma unroll
    for (int nt = 0; nt < 4; nt++)
#pragma unroll
        for (int q = 0; q < 4; q++) acc[nt][q] = 0.0f;

    const int hrow = tid >> 1;        // h-tile fill: row jj (0..127)
    const int hhalf = tid & 1;        // which 32-half chunk

#pragma unroll 1
    for (int t = 0; t < 4; t++) {
        const int j0 = jbase + t * 128;
        __syncthreads();   // previous tile's mma done reading a_s/h_s
                           // (first iteration: also covers init fills above)

        // ---- h tile: [jj][d] fp16, 128 rows ----
        {
            const uint4* src = (const uint4*)(g_h + ((size_t)b * NN + j0 + hrow) * OUT_DIM
                                              + hhalf * 32);
            uint4* dst = (uint4*)&h_s[hrow * TSH + hhalf * 32];
#pragma unroll
            for (int q = 0; q < 4; q++) dst[q] = src[q];
        }

        // ---- alpha (factorized): warp w rows w*8..w*8+7, lane covers 4 j ----
        {
            float4 e1 = *(const float4*)&E1_s[t * 128 + 4 * lane];
            float4 e2 = *(const float4*)&E2_s[t * 128 + 4 * lane];
            const int wi = (j0 >> 5) + (lane >> 3);
            const int sh = (lane & 7) * 4;
#pragma unroll
            for (int rr = 0; rr < 8; rr++) {
                int r = w * 8 + rr;
                uint32_t wb = __ldg(&g_adjbits[(size_t)(i0 + r) * NWORDS + wi]);
                uint32_t b4 = (wb >> sh) & 0xFu;
                float c1 = c1_s[r], c2 = c2_s[r], th = t_s[r];
                bool p0 = e1.x >= th, p1 = e1.y >= th, p2 = e1.z >= th, p3 = e1.w >= th;
                float al0 = (b4 & 1u) ? ((p0 ? c1 : c2) * (p0 ? e1.x : e2.x)) : 0.0f;
                float al1 = (b4 & 2u) ? ((p1 ? c1 : c2) * (p1 ? e1.y : e2.y)) : 0.0f;
                float al2 = (b4 & 4u) ? ((p2 ? c1 : c2) * (p2 ? e1.z : e2.z)) : 0.0f;
                float al3 = (b4 & 8u) ? ((p3 ? c1 : c2) * (p3 ? e1.w : e2.w)) : 0.0f;
                __stcs((float4*)(alpha_out + ((size_t)b * NN + i0 + r) * NN + j0 + 4 * lane),
                       make_float4(al0, al1, al2, al3));
                __half2 pk0 = __float22half2_rn(make_float2(al0, al1));
                __half2 pk1 = __float22half2_rn(make_float2(al2, al3));
                *(uint2*)&a_s[r * TSA + 4 * lane] =
                    make_uint2(*(uint32_t*)&pk0, *(uint32_t*)&pk1);
            }
        }
        __syncthreads();

        // ---- mma: 8 k-steps of 16, single fp16 term ----
#pragma unroll
        for (int ks = 0; ks < 8; ks++) {
            uint32_t av[4];
            ldsm_x4(av[0], av[1], av[2], av[3],
                    aB + (uint32_t)(m0 * (TSA * 2)) + laneA + (uint32_t)(ks * 32));
#pragma unroll
            for (int np = 0; np < 2; np++) {
                uint32_t bh[4];
                uint32_t boff = laneH + (uint32_t)(ks * 16 * (TSH * 2))
                              + (uint32_t)((nb + np * 16) * 2);
                ldsm_x4_t(bh[0], bh[1], bh[2], bh[3], hB + boff);
                mma16816h(acc[np * 2 + 0], av, bh[0], bh[1]);
                mma16816h(acc[np * 2 + 1], av, bh[2], bh[3]);
            }
        }
    }

    // ---- write partial ----
    float* pout = g_out_part + (size_t)jq * TOT + ((size_t)b * NN + i0) * OUT_DIM;
    int fr = lane >> 2;
    int fc = (lane & 3) * 2;
#pragma unroll
    for (int nt = 0; nt < 4; nt++) {
        int n0 = nb + nt * 8 + fc;
        __stcs((float2*)&pout[(size_t)(m0 + fr) * OUT_DIM + n0],
               make_float2(acc[nt][0], acc[nt][1]));
        __stcs((float2*)&pout[(size_t)(m0 + fr + 8) * OUT_DIM + n0],
               make_float2(acc[nt][2], acc[nt][3]));
    }

    // ---- tail: last arriver per (i-tile, b) sums 4 partials -> out ----
    __threadfence();              // publish this block's partial
    __syncthreads();
    if (tid == 0)
        last_s = (atomicAdd(&g_arrive[blockIdx.x * BATCH + b], 1) == JSPLIT - 1);
    __syncthreads();
    if (last_s) {
        __threadfence();          // acquire: see all published partials
        const size_t base = ((size_t)b * NN + i0) * OUT_DIM;   // 64*64 floats
        const int Q4 = TOT / 4;
        const float4* p = (const float4*)g_out_part;
        // 1024 float4 per cell; 256 threads -> 4 each
#pragma unroll
        for (int q = 0; q < 4; q++) {
            int idx = (int)(base / 4) + tid + q * 256;
            float4 a0 = __ldcs(p + idx);
            float4 a1 = __ldcs(p + idx + Q4);
            float4 a2 = __ldcs(p + idx + 2 * Q4);
            float4 a3 = __ldcs(p + idx + 3 * Q4);
            ((float4*)out)[idx] = make_float4(a0.x + a1.x + a2.x + a3.x,
                                              a0.y + a1.y + a2.y + a3.y,
                                              a0.z + a1.z + a2.z + a3.z,
                                              a0.w + a1.w + a2.w + a3.w);
        }
        if (tid == 0) g_arrive[blockIdx.x * BATCH + b] = 0;   // reset for next replay
    }
}

// ============================================================================
extern "C" void kernel_launch(void* const* d_in, const int* in_sizes, int n_in,
                              void* d_out, int out_size)
{
    (void)in_sizes; (void)n_in; (void)out_size;
    const float* x   = (const float*)d_in[0];   // (8, 2048, 128)
    const float* adj = (const float*)d_in[1];   // (2048, 2048)
    const float* W   = (const float*)d_in[2];   // (128, 64)
    const float* a   = (const float*)d_in[3];   // (128,)

    float* out   = (float*)d_out;                              // (8, 2048, 64)
    float* alpha = out + (size_t)BATCH * NN * OUT_DIM;         // (8, 2048, 2048)

    gat_prep_kernel<<<H_BLOCKS + (NN * NWORDS * 2) / 256, 256>>>(x, W, a, adj);

    dim3 gridB(NN / 32, BATCH);
    gat_stats_kernel<<<gridB, 256>>>();

    dim3 gridC(NN / 64, JSPLIT, BATCH);
    gat_acc_kernel<<<gridC, 256>>>(out, alpha);
}

// round 17
// speedup vs baseline: 1.4193x; 1.4193x over previous
#include <cuda_runtime.h>
#include <cuda_fp16.h>
#include <stdint.h>

#define BATCH 8
#define NN 2048
#define IN_DIM 128
#define OUT_DIM 64
#define NEG_SLOPE 0.2f
#define JSPLIT 4
#define TOT (BATCH * NN * OUT_DIM)
#define NWORDS (NN / 32)          // 64 bit-words per adj row

// ---- device scratch (allocation-free rule) ----
__device__ __half g_h[BATCH * NN * OUT_DIM];       // 2 MB, h fp16 [b][n][d]
__device__ uint32_t g_adjbits[NN * NWORDS];        // 512 KB packed adjacency
__device__ float g_fi[BATCH * NN];
__device__ float g_fj[BATCH * NN];
__device__ float g_E1[BATCH * NN];                 // exp(fj)
__device__ float g_E2[BATCH * NN];                 // exp(0.2*fj)
__device__ float g_c1[BATCH * NN];                 // sinv * exp(fi - m)
__device__ float g_c2[BATCH * NN];                 // sinv * exp(0.2*fi - m)
__device__ float g_t[BATCH * NN];                  // exp(-fi)  (branch threshold)
__device__ float g_out_part[JSPLIT * TOT];         // 16 MB

__device__ __forceinline__ float neg_inf_f() { return __int_as_float(0xff800000); }

// ---- tensor-core helpers (sm_80+ ISA: valid on base sm_100 target) ----
__device__ __forceinline__ void ldsm_x4(uint32_t& r0, uint32_t& r1, uint32_t& r2, uint32_t& r3,
                                        uint32_t addr) {
    asm volatile("ldmatrix.sync.aligned.m8n8.x4.shared.b16 {%0,%1,%2,%3}, [%4];"
                 : "=r"(r0), "=r"(r1), "=r"(r2), "=r"(r3) : "r"(addr));
}
__device__ __forceinline__ void ldsm_x4_t(uint32_t& r0, uint32_t& r1, uint32_t& r2, uint32_t& r3,
                                          uint32_t addr) {
    asm volatile("ldmatrix.sync.aligned.m8n8.x4.trans.shared.b16 {%0,%1,%2,%3}, [%4];"
                 : "=r"(r0), "=r"(r1), "=r"(r2), "=r"(r3) : "r"(addr));
}
__device__ __forceinline__ void mma16816h(float* c, const uint32_t* a, uint32_t b0, uint32_t b1) {
    asm volatile(
        "mma.sync.aligned.m16n8k16.row.col.f32.f16.f16.f32 "
        "{%0,%1,%2,%3}, {%4,%5,%6,%7}, {%8,%9}, {%0,%1,%2,%3};"
        : "+f"(c[0]), "+f"(c[1]), "+f"(c[2]), "+f"(c[3])
        : "r"(a[0]), "r"(a[1]), "r"(a[2]), "r"(a[3]), "r"(b0), "r"(b1));
}

// ============================================================================
// Kernel P: pack adj into bits. 2 threads per word (grid 1024) for occupancy.
// ============================================================================
__global__ void __launch_bounds__(256) gat_adjbits_kernel(const float* __restrict__ adj)
{
    int gt = blockIdx.x * 256 + threadIdx.x;
    int wi = gt >> 1;                 // word index
    int half = gt & 1;                // which 16 bits
    const float4* src = (const float4*)adj + (size_t)wi * 8 + half * 4;
    uint32_t bits = 0;
#pragma unroll
    for (int q = 0; q < 4; q++) {
        float4 v = src[q];
        if (v.x != 0.0f) bits |= 1u << (q * 4 + 0);
        if (v.y != 0.0f) bits |= 1u << (q * 4 + 1);
        if (v.z != 0.0f) bits |= 1u << (q * 4 + 2);
        if (v.w != 0.0f) bits |= 1u << (q * 4 + 3);
    }
    uint32_t other = __shfl_down_sync(0xffffffffu, bits, 1);
    if (half == 0) g_adjbits[wi] = bits | (other << 16);
}

// ============================================================================
// Kernel A (rewritten): h = x @ W, register-blocked 4x4 per thread.
// 64 rows/block (256 blocks). Thread (tx, ty): dims tx*4..+3, rows ty*4..+3.
// Per k4-chunk: 4 LDG.128 x (broadcast) + 4 LDS.128 W -> 64 FMA.
// k-ascending per-output order identical to previous version (bit-identical h).
// Also: fi = h.a[:64], fj = h.a[64:], E1 = exp(fj), E2 = exp(0.2 fj).
// ============================================================================
__global__ void __launch_bounds__(256) gat_h_kernel(
    const float* __restrict__ x, const float* __restrict__ W, const float* __restrict__ a)
{
    __shared__ float W_s[IN_DIM * OUT_DIM];   // 32 KB
    int tid = threadIdx.x;
    {
        const float4* Wv = (const float4*)W;
        float4* Wsv = (float4*)W_s;
#pragma unroll
        for (int i = 0; i < 8; i++) Wsv[tid + i * 256] = Wv[tid + i * 256];
    }
    __syncthreads();

    const int tx = tid & 15;          // dim group: dims tx*4..tx*4+3
    const int ty = tid >> 4;          // row group: rows ty*4..ty*4+3
    const int row0 = blockIdx.x * 64 + ty * 4;
    const float4* x4 = (const float4*)x;

    float acc[4][4];
#pragma unroll
    for (int i = 0; i < 4; i++)
#pragma unroll
        for (int j = 0; j < 4; j++) acc[i][j] = 0.0f;

#pragma unroll 2
    for (int k4 = 0; k4 < IN_DIM / 4; k4++) {
        float xv[4][4];
#pragma unroll
        for (int i = 0; i < 4; i++)
            *(float4*)xv[i] = __ldg(&x4[(size_t)(row0 + i) * (IN_DIM / 4) + k4]);
        float wv[4][4];
#pragma unroll
        for (int kk = 0; kk < 4; kk++)
            *(float4*)wv[kk] = *(const float4*)&W_s[(k4 * 4 + kk) * OUT_DIM + tx * 4];
#pragma unroll
        for (int i = 0; i < 4; i++)
#pragma unroll
            for (int j = 0; j < 4; j++)
#pragma unroll
                for (int kk = 0; kk < 4; kk++)
                    acc[i][j] = fmaf(xv[i][kk], wv[kk][j], acc[i][j]);
    }

    // ---- store h fp16 (4 rows x 4 dims = uint2 per row) ----
#pragma unroll
    for (int i = 0; i < 4; i++) {
        __half2 h0 = __float22half2_rn(make_float2(acc[i][0], acc[i][1]));
        __half2 h1 = __float22half2_rn(make_float2(acc[i][2], acc[i][3]));
        *(uint2*)(g_h + (size_t)(row0 + i) * OUT_DIM + tx * 4) =
            make_uint2(*(uint32_t*)&h0, *(uint32_t*)&h1);
    }

    // ---- fi/fj partial dots + 16-lane segment reduction ----
    float fip[4], fjp[4];
#pragma unroll
    for (int i = 0; i < 4; i++) {
        float fi = 0.0f, fj = 0.0f;
#pragma unroll
        for (int j = 0; j < 4; j++) {
            fi = fmaf(acc[i][j], __ldg(&a[tx * 4 + j]), fi);
            fj = fmaf(acc[i][j], __ldg(&a[OUT_DIM + tx * 4 + j]), fj);
        }
        fip[i] = fi; fjp[i] = fj;
    }
#pragma unroll
    for (int off = 8; off > 0; off >>= 1) {
#pragma unroll
        for (int i = 0; i < 4; i++) {
            fip[i] += __shfl_down_sync(0xffffffffu, fip[i], off, 16);
            fjp[i] += __shfl_down_sync(0xffffffffu, fjp[i], off, 16);
        }
    }
    if (tx == 0) {
#pragma unroll
        for (int i = 0; i < 4; i++) {
            int row = row0 + i;
            g_fi[row] = fip[i];
            g_fj[row] = fjp[i];
            g_E1[row] = __expf(fjp[i]);
            g_E2[row] = __expf(NEG_SLOPE * fjp[i]);
        }
    }
}

// ============================================================================
// Kernel B: stats via exp factorization — NO MUFU in the sweep.
// ============================================================================
__global__ void __launch_bounds__(256) gat_stats_kernel()
{
    __shared__ __align__(16) float fj_s[NN];   // for fjmax only
    __shared__ __align__(16) float E1_s[NN];
    __shared__ __align__(16) float E2_s[NN];
    __shared__ float red_s[8];

    int tid = threadIdx.x, lane = tid & 31, w = tid >> 5;
    int b = blockIdx.y;
    int i0 = blockIdx.x * 32;

#pragma unroll
    for (int k = 0; k < 2; k++) {
        ((float4*)fj_s)[tid + k * 256] = ((const float4*)(g_fj + (size_t)b * NN))[tid + k * 256];
        ((float4*)E1_s)[tid + k * 256] = ((const float4*)(g_E1 + (size_t)b * NN))[tid + k * 256];
        ((float4*)E2_s)[tid + k * 256] = ((const float4*)(g_E2 + (size_t)b * NN))[tid + k * 256];
    }
    __syncthreads();

    float lm = neg_inf_f();
#pragma unroll
    for (int k = 0; k < 8; k++) lm = fmaxf(lm, fj_s[tid + k * 256]);
#pragma unroll
    for (int off = 16; off > 0; off >>= 1)
        lm = fmaxf(lm, __shfl_xor_sync(0xffffffffu, lm, off));
    if (lane == 0) red_s[w] = lm;
    __syncthreads();
    float fjmax = red_s[0];
#pragma unroll
    for (int q = 1; q < 8; q++) fjmax = fmaxf(fjmax, red_s[q]);

#pragma unroll 1
    for (int rr = 0; rr < 4; rr++) {
        int r = w * 4 + rr;
        int grow = b * NN + i0 + r;
        float fi = g_fi[grow];
        float m = fi + fjmax;
        m = fmaxf(m, NEG_SLOPE * m);
        float a1 = __expf(fi - m);
        float a2 = __expf(NEG_SLOPE * fi - m);
        float t  = __expf(-fi);
        const uint32_t* brow = g_adjbits + (size_t)(i0 + r) * NWORDS;

        float S1a = 0.0f, S1b = 0.0f, S2a = 0.0f, S2b = 0.0f;
#pragma unroll 2
        for (int j = lane * 4; j < NN; j += 128) {
            uint32_t wb = __ldg(&brow[j >> 5]);
            uint32_t b4 = (wb >> (j & 31)) & 0xFu;
            float4 e1 = *(const float4*)&E1_s[j];
            float4 e2 = *(const float4*)&E2_s[j];
            if (b4 & 1u) { if (e1.x >= t) S1a += e1.x; else S2a += e2.x; }
            if (b4 & 2u) { if (e1.y >= t) S1b += e1.y; else S2b += e2.y; }
            if (b4 & 4u) { if (e1.z >= t) S1a += e1.z; else S2a += e2.z; }
            if (b4 & 8u) { if (e1.w >= t) S1b += e1.w; else S2b += e2.w; }
        }
        float s = a1 * (S1a + S1b) + a2 * (S2a + S2b);
#pragma unroll
        for (int off = 16; off > 0; off >>= 1)
            s += __shfl_xor_sync(0xffffffffu, s, off);

        if (lane == 0) {
            float si = (s > 0.0f) ? (1.0f / s) : 0.0f;
            g_c1[grow] = si * a1;
            g_c2[grow] = si * a2;
            g_t[grow]  = t;
        }
    }
}

// ============================================================================
// Kernel C: alpha (factorized) + single-term fp16 mma -> partials.
// Grid (32 i-tiles of 64, 4 j-quarters, 8 batches) = 1024 blocks.
// ============================================================================
#define TSA 136   // a_s stride in fp16 (272 B/row)
#define TSH 72    // h_s stride in fp16 (144 B/row)

__global__ void __launch_bounds__(256) gat_acc_kernel(float* __restrict__ alpha_out)
{
    __shared__ __align__(16) float E1_s[512];
    __shared__ __align__(16) float E2_s[512];
    __shared__ float c1_s[64], c2_s[64], t_s[64];
    __shared__ __align__(16) __half a_s[64 * TSA];    // 17408 B
    __shared__ __align__(16) __half h_s[128 * TSH];   // 18432 B

    int tid = threadIdx.x, lane = tid & 31, w = tid >> 5;
    int i0 = blockIdx.x * 64;
    int jq = blockIdx.y;
    int b  = blockIdx.z;
    int jbase = jq * 512;

    ((float2*)E1_s)[tid] = ((const float2*)(g_E1 + (size_t)b * NN + jbase))[tid];
    ((float2*)E2_s)[tid] = ((const float2*)(g_E2 + (size_t)b * NN + jbase))[tid];
    if (tid < 64) {
        int grow = b * NN + i0 + tid;
        c1_s[tid] = g_c1[grow];
        c2_s[tid] = g_c2[grow];
        t_s[tid]  = g_t[grow];
    }

    const uint32_t aB = (uint32_t)__cvta_generic_to_shared(a_s);
    const uint32_t hB = (uint32_t)__cvta_generic_to_shared(h_s);
    const uint32_t laneA = (uint32_t)((lane & 15) * (TSA * 2) + (lane >> 4) * 16);
    const uint32_t laneH = (uint32_t)((lane & 15) * (TSH * 2) + (lane >> 4) * 16);

    const int m0 = (w & 3) * 16;      // warp's m-strip
    const int nb = (w >> 2) * 32;     // warp's n-half

    float acc[4][4];
#pragma unroll
    for (int nt = 0; nt < 4; nt++)
#pragma unroll
        for (int q = 0; q < 4; q++) acc[nt][q] = 0.0f;

    const int hrow = tid >> 1;        // h-tile fill: row jj (0..127)
    const int hhalf = tid & 1;        // which 32-half chunk

#pragma unroll 1
    for (int t = 0; t < 4; t++) {
        const int j0 = jbase + t * 128;
        __syncthreads();   // previous tile's mma done reading a_s/h_s
                           // (first iteration: also covers init fills above)

        // ---- h tile: [jj][d] fp16, 128 rows ----
        {
            const uint4* src = (const uint4*)(g_h + ((size_t)b * NN + j0 + hrow) * OUT_DIM
                                              + hhalf * 32);
            uint4* dst = (uint4*)&h_s[hrow * TSH + hhalf * 32];
#pragma unroll
            for (int q = 0; q < 4; q++) dst[q] = src[q];
        }

        // ---- alpha (factorized): warp w rows w*8..w*8+7, lane covers 4 j ----
        {
            float4 e1 = *(const float4*)&E1_s[t * 128 + 4 * lane];
            float4 e2 = *(const float4*)&E2_s[t * 128 + 4 * lane];
            const int wi = (j0 >> 5) + (lane >> 3);
            const int sh = (lane & 7) * 4;
#pragma unroll
            for (int rr = 0; rr < 8; rr++) {
                int r = w * 8 + rr;
                uint32_t wb = __ldg(&g_adjbits[(size_t)(i0 + r) * NWORDS + wi]);
                uint32_t b4 = (wb >> sh) & 0xFu;
                float c1 = c1_s[r], c2 = c2_s[r], th = t_s[r];
                bool p0 = e1.x >= th, p1 = e1.y >= th, p2 = e1.z >= th, p3 = e1.w >= th;
                float al0 = (b4 & 1u) ? ((p0 ? c1 : c2) * (p0 ? e1.x : e2.x)) : 0.0f;
                float al1 = (b4 & 2u) ? ((p1 ? c1 : c2) * (p1 ? e1.y : e2.y)) : 0.0f;
                float al2 = (b4 & 4u) ? ((p2 ? c1 : c2) * (p2 ? e1.z : e2.z)) : 0.0f;
                float al3 = (b4 & 8u) ? ((p3 ? c1 : c2) * (p3 ? e1.w : e2.w)) : 0.0f;
                __stcs((float4*)(alpha_out + ((size_t)b * NN + i0 + r) * NN + j0 + 4 * lane),
                       make_float4(al0, al1, al2, al3));
                __half2 pk0 = __float22half2_rn(make_float2(al0, al1));
                __half2 pk1 = __float22half2_rn(make_float2(al2, al3));
                *(uint2*)&a_s[r * TSA + 4 * lane] =
                    make_uint2(*(uint32_t*)&pk0, *(uint32_t*)&pk1);
            }
        }
        __syncthreads();

        // ---- mma: 8 k-steps of 16, single fp16 term ----
#pragma unroll
        for (int ks = 0; ks < 8; ks++) {
            uint32_t av[4];
            ldsm_x4(av[0], av[1], av[2], av[3],
                    aB + (uint32_t)(m0 * (TSA * 2)) + laneA + (uint32_t)(ks * 32));
#pragma unroll
            for (int np = 0; np < 2; np++) {
                uint32_t bh[4];
                uint32_t boff = laneH + (uint32_t)(ks * 16 * (TSH * 2))
                              + (uint32_t)((nb + np * 16) * 2);
                ldsm_x4_t(bh[0], bh[1], bh[2], bh[3], hB + boff);
                mma16816h(acc[np * 2 + 0], av, bh[0], bh[1]);
                mma16816h(acc[np * 2 + 1], av, bh[2], bh[3]);
            }
        }
    }

    // ---- write partial out (streaming) ----
    float* pout = g_out_part + (size_t)jq * TOT + ((size_t)b * NN + i0) * OUT_DIM;
    int fr = lane >> 2;
    int fc = (lane & 3) * 2;
#pragma unroll
    for (int nt = 0; nt < 4; nt++) {
        int n0 = nb + nt * 8 + fc;
        __stcs((float2*)&pout[(size_t)(m0 + fr) * OUT_DIM + n0],
               make_float2(acc[nt][0], acc[nt][1]));
        __stcs((float2*)&pout[(size_t)(m0 + fr + 8) * OUT_DIM + n0],
               make_float2(acc[nt][2], acc[nt][3]));
    }
}

// ============================================================================
// Kernel D: out = sum of 4 partials (float4, streaming reads)
// ============================================================================
__global__ void __launch_bounds__(256) gat_reduce_kernel(float* __restrict__ out)
{
    int idx = blockIdx.x * 256 + threadIdx.x;
    const float4* p = (const float4*)g_out_part;
    const int Q4 = TOT / 4;
    float4 a0 = __ldcs(p + idx);
    float4 a1 = __ldcs(p + idx + Q4);
    float4 a2 = __ldcs(p + idx + 2 * Q4);
    float4 a3 = __ldcs(p + idx + 3 * Q4);
    ((float4*)out)[idx] = make_float4(a0.x + a1.x + a2.x + a3.x,
                                      a0.y + a1.y + a2.y + a3.y,
                                      a0.z + a1.z + a2.z + a3.z,
                                      a0.w + a1.w + a2.w + a3.w);
}

// ============================================================================
extern "C" void kernel_launch(void* const* d_in, const int* in_sizes, int n_in,
                              void* d_out, int out_size)
{
    (void)in_sizes; (void)n_in; (void)out_size;
    const float* x   = (const float*)d_in[0];   // (8, 2048, 128)
    const float* adj = (const float*)d_in[1];   // (2048, 2048)
    const float* W   = (const float*)d_in[2];   // (128, 64)
    const float* a   = (const float*)d_in[3];   // (128,)

    float* out   = (float*)d_out;                              // (8, 2048, 64)
    float* alpha = out + (size_t)BATCH * NN * OUT_DIM;         // (8, 2048, 2048)

    gat_adjbits_kernel<<<(NN * NWORDS * 2) / 256, 256>>>(adj);
    gat_h_kernel<<<(BATCH * NN) / 64, 256>>>(x, W, a);

    dim3 gridB(NN / 32, BATCH);
    gat_stats_kernel<<<gridB, 256>>>();

    dim3 gridC(NN / 64, JSPLIT, BATCH);
    gat_acc_kernel<<<gridC, 256>>>(alpha);

    gat_reduce_kernel<<<(TOT / 4) / 256, 256>>>(out);
}